// round 9
// baseline (speedup 1.0000x reference)
#include <cuda_runtime.h>
#include <math.h>

typedef unsigned long long u64;

#define NE   16
#define NN   4
#define DIM  128
#define KD   64
#define FD   32
#define HD   45
#define HP   48
#define HST  48      // hid row stride (floats)
#define ES   112
#define EA   128
#define ENE  64
#define ET   304

// ---- shared memory layout (floats) ----
#define OFF_FEATS 0
#define SZ_FEATS  (16 * ET * 2)          // 9728: featsP[fp][e] u64 (f-pair per edge)
#define OFF_ELEC  (OFF_FEATS + SZ_FEATS) // 9728
#define SZ_ELEC   (NE * DIM)             // 2048
#define OFF_HX    (OFF_ELEC + SZ_ELEC)   // 11776
#define SZ_HX     (2 * NE * KD)          // 2048
#define OFF_UNI   (OFF_HX + SZ_HX)       // 13824
#define SZ_UNI    (DIM * 34 * 2)         // 8704: gp[d][34]u64 / wp[dp][64]u64 8192 / hid 6144
#define OFF_W1P   (OFF_UNI + SZ_UNI)     // 22528
#define SZ_W1P    (16 * HP * 2)          // 1536: w1p[fp][h] u64
#define OFF_B1    (OFF_W1P + SZ_W1P)     // 24064
#define SZ_B1     (HP)                   // 48
#define OFF_W2P   (OFF_B1 + SZ_B1)       // 24112
#define SZ_W2P    (24 * KD * 2)          // 3072: w2p[hp][k] u64
#define OFF_Z     (OFF_W2P + SZ_W2P)     // 27184
#define SZ_Z      (NE * KD)              // 1024
#define OFF_YW    (OFF_Z + SZ_Z)         // 28208
#define SZ_YW     (NN * KD)              // 256
#define SMEM_FLOATS (OFF_YW + SZ_YW)     // 28464 floats = 113,856 B

__device__ __forceinline__ void ffma2(u64& d, u64 a, u64 b) {
    asm("fma.rn.f32x2 %0, %1, %2, %0;" : "+l"(d) : "l"(a), "l"(b));
}
__device__ __forceinline__ float hsum2(u64 v) {
    unsigned int lo, hi;
    asm("mov.b64 {%0, %1}, %2;" : "=r"(lo), "=r"(hi) : "l"(v));
    return __uint_as_float(lo) + __uint_as_float(hi);
}
__device__ __forceinline__ float silu_f(float x) {
    return x / (1.0f + __expf(-x));
}

// stage packed W1 (u64 [16][HP]), b1, packed W2 (u64 [24][KD]) for weight-set lj
__device__ __forceinline__ void stage_w12(const float* __restrict__ wW1,
                                          const float* __restrict__ wb1,
                                          const float* __restrict__ wW2,
                                          int lj, float* w1p, float* b1s,
                                          float* w2p, int tid)
{
    const float* W1 = wW1 + (size_t)lj * FD * HD;
    for (int i = tid; i < 16 * HP; i += 256) {
        int fp = i / HP, h = i - fp * HP;
        float lo = (h < HD) ? W1[(2 * fp) * HD + h] : 0.f;
        float hi = (h < HD) ? W1[(2 * fp + 1) * HD + h] : 0.f;
        *(float2*)&w1p[i * 2] = make_float2(lo, hi);
    }
    if (tid < HP) {
        const float* B1 = wb1 + (size_t)lj * HD;
        b1s[tid] = (tid < HD) ? B1[tid] : 0.f;
    }
    const float* W2 = wW2 + (size_t)lj * HD * KD;
    for (int i = tid; i < 24 * KD; i += 256) {
        int hp = i >> 6, k = i & 63;
        int h0 = 2 * hp, h1 = 2 * hp + 1;
        float lo = (h0 < HD) ? W2[h0 * KD + k] : 0.f;
        float hi = (h1 < HD) ? W2[h1 * KD + k] : 0.f;
        *(float2*)&w2p[i * 2] = make_float2(lo, hi);
    }
}

// fused MLP2 (packed over h-parity) + gather-product into z, batch of CNT<=4 edges
template<int CNT>
__device__ __forceinline__ void fusedz_batch(const float* __restrict__ sm,
                                             const float* __restrict__ hid,
                                             const float* __restrict__ w2p,
                                             const int* eoff, const int* hxo,
                                             int k0, float4& zacc)
{
    u64 acc[CNT][4];
    #pragma unroll
    for (int e = 0; e < CNT; e++)
        { acc[e][0] = 0; acc[e][1] = 0; acc[e][2] = 0; acc[e][3] = 0; }

    #pragma unroll 4
    for (int hp = 0; hp < 24; hp++) {
        ulonglong2 wA = *(const ulonglong2*)&w2p[(hp * KD + k0) * 2];
        ulonglong2 wB = *(const ulonglong2*)&w2p[(hp * KD + k0 + 2) * 2];
        #pragma unroll
        for (int e = 0; e < CNT; e++) {
            u64 hv = *(const u64*)&hid[eoff[e] + 2 * hp];
            ffma2(acc[e][0], hv, wA.x);
            ffma2(acc[e][1], hv, wA.y);
            ffma2(acc[e][2], hv, wB.x);
            ffma2(acc[e][3], hv, wB.y);
        }
    }
    #pragma unroll
    for (int e = 0; e < CNT; e++) {
        float4 hv = *(const float4*)&sm[hxo[e] + k0];
        zacc.x += hsum2(acc[e][0]) * hv.x;
        zacc.y += hsum2(acc[e][1]) * hv.y;
        zacc.z += hsum2(acc[e][2]) * hv.z;
        zacc.w += hsum2(acc[e][3]) * hv.w;
    }
}

__global__ void __launch_bounds__(256, 2)
schnet_kernel(const float* __restrict__ rs,    const float* __restrict__ coords,
              const float* __restrict__ X_tab, const float* __restrict__ Y_w,
              const float* __restrict__ wW1,   const float* __restrict__ wb1,
              const float* __restrict__ wW2,   const float* __restrict__ h0t,
              const float* __restrict__ hW,    const float* __restrict__ gW,
              const int* __restrict__ same_s,  const int* __restrict__ same_r,
              const int* __restrict__ anti_s,  const int* __restrict__ anti_r,
              const int* __restrict__ ne_s,    const int* __restrict__ ne_r,
              float* __restrict__ out)
{
    extern __shared__ float sm[];
    const int b   = blockIdx.x;
    const int tid = threadIdx.x;

    float* featsP = sm + OFF_FEATS;   // u64 view: [16 fp][304 e]
    float* elec   = sm + OFF_ELEC;
    float* hx     = sm + OFF_HX;
    float* uni    = sm + OFF_UNI;     // hid [e][48] | wp u64 [64][64] | gp u64 [128][34]
    float* w1p    = sm + OFF_W1P;
    float* b1s    = sm + OFF_B1;
    float* w2p    = sm + OFF_W2P;
    float* z_s    = sm + OFF_Z;
    float* yw_s   = sm + OFF_YW;

    // ---- init ----
    for (int i = tid; i < NE * DIM; i += 256) elec[i] = X_tab[i & (DIM - 1)];
    for (int i = tid; i < NN * KD;  i += 256) yw_s[i] = Y_w[i];

    // ---- featurize: once per sample; store f-pair-packed [fp][e] ----
    const float* rsb = rs + (size_t)b * NE * 3;
    for (int e = tid; e < ET; e += 256) {
        float sx, sy, sz2;
        int r;
        if (e < ES) {
            int s = same_s[e]; r = same_r[e];
            sx = rsb[s*3]; sy = rsb[s*3+1]; sz2 = rsb[s*3+2];
        } else if (e < ES + EA) {
            int q = e - ES; int s = anti_s[q]; r = anti_r[q];
            sx = rsb[s*3]; sy = rsb[s*3+1]; sz2 = rsb[s*3+2];
        } else {
            int q = e - ES - EA; int n = ne_s[q]; r = ne_r[q];
            sx = coords[n*3]; sy = coords[n*3+1]; sz2 = coords[n*3+2];
        }
        float dx = sx - rsb[r*3], dy = sy - rsb[r*3+1], dz = sz2 - rsb[r*3+2];
        float d   = sqrtf(dx*dx + dy*dy + dz*dz);
        float env = d * d * __expf(-d);
        float fv[FD];
        #pragma unroll
        for (int i = 0; i < FD; i++) {
            float q  = (float)i * (1.0f / 31.0f);
            float mu = 10.0f * q * q;
            float sg = (1.0f + 10.0f * q) * (1.0f / 7.0f);
            float t  = (d - mu) / sg;
            fv[i] = env * __expf(-t * t);
        }
        #pragma unroll
        for (int fp = 0; fp < 16; fp++)
            *(float2*)&featsP[(fp * ET + e) * 2] = make_float2(fv[2*fp], fv[2*fp+1]);
    }
    stage_w12(wW1, wb1, wW2, 0, w1p, b1s, w2p, tid);
    __syncthreads();

    for (int l = 0; l < 3; l++) {
        // ---- hx (from elec BEFORE this layer's in-place update) ----
        if (l == 0) {
            for (int i = tid; i < 2 * NE * KD; i += 256)
                hx[i] = h0t[((i >> 10) << 6) + (i & (KD - 1))];
            __syncthreads();
        } else {
            for (int j2 = 0; j2 < 2; j2++) {
                // stage hW packed over d-pairs: wp[dp][k] u64, into uni
                const float* src = hW + (size_t)((l - 1) * 2 + j2) * DIM * KD;
                for (int i = tid; i < 64 * KD; i += 256) {
                    int dp = i >> 6, k = i & 63;
                    *(float2*)&uni[i * 2] =
                        make_float2(src[(2*dp) * KD + k], src[(2*dp+1) * KD + k]);
                }
                __syncthreads();
                int s  = tid >> 4;
                int k0 = (tid & 15) << 2;
                u64 acc[4] = {0, 0, 0, 0};
                #pragma unroll 8
                for (int dp = 0; dp < 64; dp++) {
                    u64 ev = *(const u64*)&elec[s * DIM + 2 * dp];
                    ulonglong2 wA = *(const ulonglong2*)&uni[(dp * KD + k0) * 2];
                    ulonglong2 wB = *(const ulonglong2*)&uni[(dp * KD + k0 + 2) * 2];
                    ffma2(acc[0], ev, wA.x);
                    ffma2(acc[1], ev, wA.y);
                    ffma2(acc[2], ev, wB.x);
                    ffma2(acc[3], ev, wB.y);
                }
                __syncthreads();   // uni reads done before next overwrite
                *(float4*)&hx[j2 * NE * KD + s * KD + k0] =
                    make_float4(hsum2(acc[0]), hsum2(acc[1]),
                                hsum2(acc[2]), hsum2(acc[3]));
            }
            __syncthreads();
        }

        for (int j = 0; j < 3; j++) {
            const int lj   = l * 3 + j;
            const int Ej   = (j == 0) ? ES : (j == 1) ? EA : ENE;
            const int foff = (j == 0) ? 0  : (j == 1) ? ES : (ES + EA);

            // ---- phase A: MLP1 packed over f-parity; 4 edges x 4 h per tile ----
            {
                float* hid = uni;
                int ntile = (Ej >> 2) * 12;
                for (int t = tid; t < ntile; t += 256) {
                    int rg = t / 12, cg = t - rg * 12;
                    int r0 = rg << 2, hc = cg << 2;
                    int ge0 = foff + r0;
                    u64 acc[4][4];
                    #pragma unroll
                    for (int e = 0; e < 4; e++)
                        { acc[e][0]=0; acc[e][1]=0; acc[e][2]=0; acc[e][3]=0; }
                    #pragma unroll 4
                    for (int fp = 0; fp < 16; fp++) {
                        ulonglong2 x01 = *(const ulonglong2*)&featsP[(fp * ET + ge0) * 2];
                        ulonglong2 x23 = *(const ulonglong2*)&featsP[(fp * ET + ge0 + 2) * 2];
                        ulonglong2 w01 = *(const ulonglong2*)&w1p[(fp * HP + hc) * 2];
                        ulonglong2 w23 = *(const ulonglong2*)&w1p[(fp * HP + hc + 2) * 2];
                        ffma2(acc[0][0], x01.x, w01.x); ffma2(acc[0][1], x01.x, w01.y);
                        ffma2(acc[0][2], x01.x, w23.x); ffma2(acc[0][3], x01.x, w23.y);
                        ffma2(acc[1][0], x01.y, w01.x); ffma2(acc[1][1], x01.y, w01.y);
                        ffma2(acc[1][2], x01.y, w23.x); ffma2(acc[1][3], x01.y, w23.y);
                        ffma2(acc[2][0], x23.x, w01.x); ffma2(acc[2][1], x23.x, w01.y);
                        ffma2(acc[2][2], x23.x, w23.x); ffma2(acc[2][3], x23.x, w23.y);
                        ffma2(acc[3][0], x23.y, w01.x); ffma2(acc[3][1], x23.y, w01.y);
                        ffma2(acc[3][2], x23.y, w23.x); ffma2(acc[3][3], x23.y, w23.y);
                    }
                    float4 bb = *(const float4*)&b1s[hc];
                    #pragma unroll
                    for (int e = 0; e < 4; e++) {
                        float4 o;
                        o.x = silu_f(hsum2(acc[e][0]) + bb.x);
                        o.y = silu_f(hsum2(acc[e][1]) + bb.y);
                        o.z = silu_f(hsum2(acc[e][2]) + bb.z);
                        o.w = silu_f(hsum2(acc[e][3]) + bb.w);
                        *(float4*)&hid[(r0 + e) * HST + hc] = o;
                    }
                }
            }
            __syncthreads();

            // ---- phase B: fused MLP2 (h-parity packed) + segment-sum -> z ----
            {
                int r  = tid >> 4;
                int k0 = (tid & 15) << 2;
                float4 zacc = make_float4(0.f, 0.f, 0.f, 0.f);
                if (j == 0) {
                    int base = (r < 8) ? 0 : 56;
                    int rr   = r & 7;
                    int sb   = (r < 8) ? 0 : 8;
                    int eoff[7], hxo[7];
                    int c = 0;
                    #pragma unroll
                    for (int ss = 0; ss < 8; ss++) {
                        if (ss == rr) continue;
                        eoff[c] = (base + ss * 7 + ((rr < ss) ? rr : rr - 1)) * HST;
                        hxo[c]  = OFF_HX + (sb + ss) * KD;
                        c++;
                    }
                    fusedz_batch<4>(sm, uni, w2p, eoff,     hxo,     k0, zacc);
                    fusedz_batch<3>(sm, uni, w2p, eoff + 4, hxo + 4, k0, zacc);
                } else if (j == 1) {
                    int eoff[8], hxo[8];
                    #pragma unroll
                    for (int ss = 0; ss < 8; ss++) {
                        int eidx, sg;
                        if (r < 8) { eidx = 64 + ss * 8 + r;  sg = ss + 8; }
                        else       { eidx = ss * 8 + (r - 8); sg = ss;     }
                        eoff[ss] = eidx * HST;
                        hxo[ss]  = OFF_HX + NE * KD + sg * KD;
                    }
                    fusedz_batch<4>(sm, uni, w2p, eoff,     hxo,     k0, zacc);
                    fusedz_batch<4>(sm, uni, w2p, eoff + 4, hxo + 4, k0, zacc);
                } else {
                    int eoff[4], hxo[4];
                    #pragma unroll
                    for (int n = 0; n < 4; n++) {
                        eoff[n] = (n * 16 + r) * HST;
                        hxo[n]  = OFF_YW + n * KD;
                    }
                    fusedz_batch<4>(sm, uni, w2p, eoff, hxo, k0, zacc);
                }
                *(float4*)&z_s[r * KD + k0] = zacc;
            }
            __syncthreads();

            // ---- phase C: stage gW k-pair-packed gp[d][34]u64 -> uni;
            //      prefetch next lj's W1/b1/W2 ----
            {
                const float* G = gW + (size_t)lj * KD * DIM;
                for (int i = tid; i < 32 * DIM; i += 256) {
                    int kp = i >> 7, d = i & 127;
                    *(float2*)&uni[(d * 34 + kp) * 2] =
                        make_float2(G[(2*kp) * DIM + d], G[(2*kp+1) * DIM + d]);
                }
                if (lj < 8) stage_w12(wW1, wb1, wW2, lj + 1, w1p, b1s, w2p, tid);
            }
            __syncthreads();

            // ---- phase D: elec += z @ gW (k-parity packed, in place) ----
            {
                int rg   = tid >> 5;
                int lane = tid & 31;
                u64 a0[4] = {0,0,0,0};
                u64 a1[4] = {0,0,0,0};
                #pragma unroll 4
                for (int kb = 0; kb < 16; kb++) {
                    ulonglong2 z0 = *(const ulonglong2*)&z_s[rg * KD + 4 * kb];
                    ulonglong2 z1 = *(const ulonglong2*)&z_s[(rg + 8) * KD + 4 * kb];
                    #pragma unroll
                    for (int q = 0; q < 4; q++) {
                        int d = lane + 32 * q;
                        ulonglong2 g = *(const ulonglong2*)&uni[(d * 34 + 2 * kb) * 2];
                        ffma2(a0[q], z0.x, g.x); ffma2(a0[q], z0.y, g.y);
                        ffma2(a1[q], z1.x, g.x); ffma2(a1[q], z1.y, g.y);
                    }
                }
                #pragma unroll
                for (int q = 0; q < 4; q++) {
                    int d = lane + 32 * q;
                    elec[rg * DIM + d]       += hsum2(a0[q]);
                    elec[(rg + 8) * DIM + d] += hsum2(a1[q]);
                }
            }
            __syncthreads();
        } // j
    } // l

    // ---- write out ----
    float4* op = (float4*)(out + (size_t)b * NE * DIM);
    const float4* ep = (const float4*)elec;
    for (int i = tid; i < (NE * DIM) / 4; i += 256) op[i] = ep[i];
}

extern "C" void kernel_launch(void* const* d_in, const int* in_sizes, int n_in,
                              void* d_out, int out_size) {
    const float* rs     = (const float*)d_in[0];
    const float* coords = (const float*)d_in[1];
    const float* X_tab  = (const float*)d_in[2];
    const float* Y_w    = (const float*)d_in[3];
    const float* wW1    = (const float*)d_in[4];
    const float* wb1    = (const float*)d_in[5];
    const float* wW2    = (const float*)d_in[6];
    const float* h0t    = (const float*)d_in[7];
    const float* hW     = (const float*)d_in[8];
    const float* gW     = (const float*)d_in[9];
    const int* same_s   = (const int*)d_in[10];
    const int* same_r   = (const int*)d_in[11];
    const int* anti_s   = (const int*)d_in[12];
    const int* anti_r   = (const int*)d_in[13];
    const int* ne_s     = (const int*)d_in[14];
    const int* ne_r     = (const int*)d_in[15];

    int B = in_sizes[0] / (NE * 3);
    size_t smem_bytes = (size_t)SMEM_FLOATS * sizeof(float);
    cudaFuncSetAttribute(schnet_kernel,
                         cudaFuncAttributeMaxDynamicSharedMemorySize,
                         (int)smem_bytes);
    schnet_kernel<<<B, 256, smem_bytes>>>(rs, coords, X_tab, Y_w, wW1, wb1, wW2,
                                          h0t, hW, gW, same_s, same_r,
                                          anti_s, anti_r, ne_s, ne_r,
                                          (float*)d_out);
}